// round 9
// baseline (speedup 1.0000x reference)
#include <cuda_runtime.h>
#include <cuda_bf16.h>
#include <cstdint>

// ---------------- problem constants ----------------
#define NNODES 50000
#define NEDGES 800000
#define SCAN_B 256
#define NBLK   ((NNODES + SCAN_B - 1) / SCAN_B)   // 196

// ---------------- device scratch (no allocs allowed) ----------------
__device__ int   g_is32;
__device__ int   g_src[NEDGES];
__device__ int   g_dst[NEDGES];
__device__ int   g_deg[NNODES];
__device__ int   g_rowptr[NNODES + 1];
__device__ int   g_fill[NNODES];
__device__ int   g_csrc[NEDGES];
__device__ int   g_bsum[NBLK];
__device__ float g_dinv[NNODES];
__device__ uint2 g_zb[NNODES * 32];     // z bf16: 128 cols = 32 uint2
__device__ float g_y[NNODES * 128];
__device__ float g_h[NNODES * 128];

__device__ __forceinline__ float to_tf32(float x) {
    float r;
    asm("cvt.rna.tf32.f32 %0, %1;" : "=f"(r) : "f"(x));
    return r;
}

// ---------------- dtype detect ----------------
__global__ void k_detect(const long long* __restrict__ ei64) {
    int t = threadIdx.x + blockIdx.x * blockDim.x;
    long long stride = NEDGES / 4096;
    long long v = ei64[(long long)t * stride];
    if (v < 0 || v >= NNODES) atomicOr(&g_is32, 1);
}

// ---------------- edge decode + degree ----------------
__global__ void k_prep_edges(const void* __restrict__ ei_raw) {
    int i = blockIdx.x * blockDim.x + threadIdx.x;
    if (i >= NEDGES) return;
    int d, s;
    if (g_is32) {
        const int* e = (const int*)ei_raw;
        d = e[i]; s = e[NEDGES + i];
    } else {
        const long long* e = (const long long*)ei_raw;
        d = (int)e[i]; s = (int)e[NEDGES + i];
    }
    g_dst[i] = d;
    g_src[i] = s;
    atomicAdd(&g_deg[d], 1);
}

// ---------------- CSR build ----------------
__global__ void k_scan1() {
    __shared__ int s[SCAN_B];
    int tid = threadIdx.x;
    int i = blockIdx.x * SCAN_B + tid;
    int v = (i < NNODES) ? g_deg[i] : 0;
    s[tid] = v;
    __syncthreads();
    #pragma unroll
    for (int off = 1; off < SCAN_B; off <<= 1) {
        int t = (tid >= off) ? s[tid - off] : 0;
        __syncthreads();
        s[tid] += t;
        __syncthreads();
    }
    if (i < NNODES) g_rowptr[i + 1] = s[tid];
    if (tid == SCAN_B - 1) g_bsum[blockIdx.x] = s[tid];
}

__global__ void k_scan3() {
    __shared__ int red[SCAN_B];
    int tid = threadIdx.x;
    int part = (tid < (int)blockIdx.x && tid < NBLK) ? g_bsum[tid] : 0;
    red[tid] = part;
    __syncthreads();
    #pragma unroll
    for (int off = SCAN_B / 2; off > 0; off >>= 1) {
        if (tid < off) red[tid] += red[tid + off];
        __syncthreads();
    }
    int offset = red[0];
    int i = blockIdx.x * SCAN_B + tid;
    if (i == 0) g_rowptr[0] = 0;
    if (i < NNODES) {
        g_rowptr[i + 1] += offset;
        g_dinv[i] = 1.0f / fmaxf((float)g_deg[i], 1.0f);
    }
}
__global__ void k_fill() {
    int i = blockIdx.x * blockDim.x + threadIdx.x;
    if (i >= NEDGES) return;
    int d = g_dst[i];
    int pos = g_rowptr[d] + atomicAdd(&g_fill[d], 1);
    g_csrc[pos] = g_src[i];
}

// ---------------- mma.sync tf32 dual GEMM ----------------
template <int NC>
__global__ __launch_bounds__(512, 1)
void k_gemm_mma(const float* __restrict__ H,
                const float* __restrict__ Wl, const float* __restrict__ Wr,
                __nv_bfloat162* __restrict__ Zb, float* __restrict__ Y) {
    constexpr int D   = NC / 2;
    constexpr int NT  = NC / 32;
    constexpr int ST  = 132;

    extern __shared__ float smem[];
    float* sA = smem;
    float* sB = smem + 128 * ST;

    const int tid  = threadIdx.x;
    const int wid  = tid >> 5;
    const int lane = tid & 31;
    const int row0 = blockIdx.x * 128;

    {
        const float4* h4 = (const float4*)H;
        #pragma unroll
        for (int i = tid; i < 128 * 32; i += 512) {
            int r = i >> 5, c = i & 31;
            int gr = row0 + r;
            float4 v = make_float4(0.f, 0.f, 0.f, 0.f);
            if (gr < NNODES) v = h4[gr * 32 + c];
            float* p = &sA[r * ST + c * 4];
            p[0] = to_tf32(v.x); p[1] = to_tf32(v.y);
            p[2] = to_tf32(v.z); p[3] = to_tf32(v.w);
        }
    }
    {
        #pragma unroll
        for (int i = tid; i < NC * 32; i += 512) {
            int n = i >> 5, c = i & 31;
            const float4* wsrc = (const float4*)((n < D) ? (Wl + n * 128)
                                                         : (Wr + (n - D) * 128));
            float4 v = wsrc[c];
            float* p = &sB[n * ST + c * 4];
            p[0] = to_tf32(v.x); p[1] = to_tf32(v.y);
            p[2] = to_tf32(v.z); p[3] = to_tf32(v.w);
        }
    }
    __syncthreads();

    const int warp_m = wid & 3;
    const int warp_n = wid >> 2;
    const int lm = lane >> 2;
    const int lk = lane & 3;

    float acc[2][NT][4];
    #pragma unroll
    for (int mi = 0; mi < 2; ++mi)
        #pragma unroll
        for (int ni = 0; ni < NT; ++ni)
            #pragma unroll
            for (int q = 0; q < 4; ++q) acc[mi][ni][q] = 0.f;

    #pragma unroll
    for (int kk = 0; kk < 16; ++kk) {
        const int k0 = kk * 8;
        uint32_t a[2][4];
        #pragma unroll
        for (int mi = 0; mi < 2; ++mi) {
            const int rb = warp_m * 32 + mi * 16;
            a[mi][0] = *(const uint32_t*)&sA[(rb + lm)     * ST + k0 + lk];
            a[mi][1] = *(const uint32_t*)&sA[(rb + 8 + lm) * ST + k0 + lk];
            a[mi][2] = *(const uint32_t*)&sA[(rb + lm)     * ST + k0 + 4 + lk];
            a[mi][3] = *(const uint32_t*)&sA[(rb + 8 + lm) * ST + k0 + 4 + lk];
        }
        uint32_t b[NT][2];
        #pragma unroll
        for (int ni = 0; ni < NT; ++ni) {
            const int nb = warp_n * (NT * 8) + ni * 8;
            b[ni][0] = *(const uint32_t*)&sB[(nb + lm) * ST + k0 + lk];
            b[ni][1] = *(const uint32_t*)&sB[(nb + lm) * ST + k0 + 4 + lk];
        }
        #pragma unroll
        for (int mi = 0; mi < 2; ++mi)
            #pragma unroll
            for (int ni = 0; ni < NT; ++ni) {
                asm volatile(
                    "mma.sync.aligned.m16n8k8.row.col.f32.tf32.tf32.f32 "
                    "{%0,%1,%2,%3}, {%4,%5,%6,%7}, {%8,%9}, {%0,%1,%2,%3};"
                    : "+f"(acc[mi][ni][0]), "+f"(acc[mi][ni][1]),
                      "+f"(acc[mi][ni][2]), "+f"(acc[mi][ni][3])
                    : "r"(a[mi][0]), "r"(a[mi][1]), "r"(a[mi][2]), "r"(a[mi][3]),
                      "r"(b[ni][0]), "r"(b[ni][1]));
            }
    }

    {
        const bool yhalf = (warp_n >= 2);
        const int cbase = warp_n * (NT * 8) - (yhalf ? D : 0);
        #pragma unroll
        for (int mi = 0; mi < 2; ++mi) {
            const int rl = row0 + warp_m * 32 + mi * 16 + lm;
            const int rh = rl + 8;
            #pragma unroll
            for (int ni = 0; ni < NT; ++ni) {
                const int oc = cbase + ni * 8 + lk * 2;
                if (yhalf) {
                    if (rl < NNODES)
                        *(float2*)&Y[rl * D + oc] = make_float2(acc[mi][ni][0], acc[mi][ni][1]);
                    if (rh < NNODES)
                        *(float2*)&Y[rh * D + oc] = make_float2(acc[mi][ni][2], acc[mi][ni][3]);
                } else {
                    if (rl < NNODES)
                        Zb[rl * (D / 2) + oc / 2] =
                            __float22bfloat162_rn(make_float2(acc[mi][ni][0], acc[mi][ni][1]));
                    if (rh < NNODES)
                        Zb[rh * (D / 2) + oc / 2] =
                            __float22bfloat162_rn(make_float2(acc[mi][ni][2], acc[mi][ni][3]));
                }
            }
        }
    }
}

// -------- gather + combine + relu (D=128): warp/node, batched indices ------
__global__ __launch_bounds__(256)
void k_gather_combine128(const uint2* __restrict__ Zb, const float* __restrict__ Yb,
                         const float* __restrict__ bias, float* __restrict__ Hout) {
    const int w    = (blockIdx.x * blockDim.x + threadIdx.x) >> 5;
    const int lane = threadIdx.x & 31;
    if (w >= NNODES) return;
    int j = g_rowptr[w];
    const int e = g_rowptr[w + 1];
    float4 a0 = make_float4(0.f, 0.f, 0.f, 0.f);
    float4 a1 = make_float4(0.f, 0.f, 0.f, 0.f);
    float4 a2 = make_float4(0.f, 0.f, 0.f, 0.f);
    float4 a3 = make_float4(0.f, 0.f, 0.f, 0.f);
    while (j < e) {
        const int last = e - 1;
        int jl = j + lane;
        const int idx = g_csrc[jl <= last ? jl : last];   // coalesced 32-index prefetch
        const int n = min(e - j, 32);
        int t = 0;
        for (; t + 4 <= n; t += 4) {
            int s0 = __shfl_sync(0xffffffffu, idx, t);
            int s1 = __shfl_sync(0xffffffffu, idx, t + 1);
            int s2 = __shfl_sync(0xffffffffu, idx, t + 2);
            int s3 = __shfl_sync(0xffffffffu, idx, t + 3);
            uint2 u0 = Zb[s0 * 32 + lane];
            uint2 u1 = Zb[s1 * 32 + lane];
            uint2 u2 = Zb[s2 * 32 + lane];
            uint2 u3 = Zb[s3 * 32 + lane];
            float2 f;
            f = __bfloat1622float2(*(const __nv_bfloat162*)&u0.x); a0.x += f.x; a0.y += f.y;
            f = __bfloat1622float2(*(const __nv_bfloat162*)&u0.y); a0.z += f.x; a0.w += f.y;
            f = __bfloat1622float2(*(const __nv_bfloat162*)&u1.x); a1.x += f.x; a1.y += f.y;
            f = __bfloat1622float2(*(const __nv_bfloat162*)&u1.y); a1.z += f.x; a1.w += f.y;
            f = __bfloat1622float2(*(const __nv_bfloat162*)&u2.x); a2.x += f.x; a2.y += f.y;
            f = __bfloat1622float2(*(const __nv_bfloat162*)&u2.y); a2.z += f.x; a2.w += f.y;
            f = __bfloat1622float2(*(const __nv_bfloat162*)&u3.x); a3.x += f.x; a3.y += f.y;
            f = __bfloat1622float2(*(const __nv_bfloat162*)&u3.y); a3.z += f.x; a3.w += f.y;
        }
        for (; t < n; ++t) {
            int s0 = __shfl_sync(0xffffffffu, idx, t);
            uint2 u0 = Zb[s0 * 32 + lane];
            float2 f;
            f = __bfloat1622float2(*(const __nv_bfloat162*)&u0.x); a0.x += f.x; a0.y += f.y;
            f = __bfloat1622float2(*(const __nv_bfloat162*)&u0.y); a0.z += f.x; a0.w += f.y;
        }
        j += n;
    }
    a0.x += a1.x + a2.x + a3.x;
    a0.y += a1.y + a2.y + a3.y;
    a0.z += a1.z + a2.z + a3.z;
    a0.w += a1.w + a2.w + a3.w;
    float inv = g_dinv[w];
    float4 yv = ((const float4*)Yb)[w * 32 + lane];
    float4 bv = ((const float4*)bias)[lane];
    float4 o;
    o.x = fmaxf(a0.x * inv + yv.x + bv.x, 0.f);
    o.y = fmaxf(a0.y * inv + yv.y + bv.y, 0.f);
    o.z = fmaxf(a0.z * inv + yv.z + bv.z, 0.f);
    o.w = fmaxf(a0.w * inv + yv.w + bv.w, 0.f);
    ((float4*)Hout)[w * 32 + lane] = o;
}

// -------- gather + combine + log_softmax (D=64): batched indices --------
__global__ __launch_bounds__(256)
void k_gather_final64(const unsigned* __restrict__ Zb, const float* __restrict__ Yb,
                      const float* __restrict__ bias, float* __restrict__ out) {
    const int w    = (blockIdx.x * blockDim.x + threadIdx.x) >> 5;
    const int lane = threadIdx.x & 31;
    if (w >= NNODES) return;
    int j = g_rowptr[w];
    const int e = g_rowptr[w + 1];
    float2 a0 = make_float2(0.f, 0.f);
    float2 a1 = make_float2(0.f, 0.f);
    float2 a2 = make_float2(0.f, 0.f);
    float2 a3 = make_float2(0.f, 0.f);
    while (j < e) {
        const int last = e - 1;
        int jl = j + lane;
        const int idx = g_csrc[jl <= last ? jl : last];
        const int n = min(e - j, 32);
        int t = 0;
        for (; t + 4 <= n; t += 4) {
            int s0 = __shfl_sync(0xffffffffu, idx, t);
            int s1 = __shfl_sync(0xffffffffu, idx, t + 1);
            int s2 = __shfl_sync(0xffffffffu, idx, t + 2);
            int s3 = __shfl_sync(0xffffffffu, idx, t + 3);
            unsigned u0 = Zb[s0 * 32 + lane];
            unsigned u1 = Zb[s1 * 32 + lane];
            unsigned u2 = Zb[s2 * 32 + lane];
            unsigned u3 = Zb[s3 * 32 + lane];
            float2 f;
            f = __bfloat1622float2(*(const __nv_bfloat162*)&u0); a0.x += f.x; a0.y += f.y;
            f = __bfloat1622float2(*(const __nv_bfloat162*)&u1); a1.x += f.x; a1.y += f.y;
            f = __bfloat1622float2(*(const __nv_bfloat162*)&u2); a2.x += f.x; a2.y += f.y;
            f = __bfloat1622float2(*(const __nv_bfloat162*)&u3); a3.x += f.x; a3.y += f.y;
        }
        for (; t < n; ++t) {
            int s0 = __shfl_sync(0xffffffffu, idx, t);
            unsigned u0 = Zb[s0 * 32 + lane];
            float2 f = __bfloat1622float2(*(const __nv_bfloat162*)&u0);
            a0.x += f.x; a0.y += f.y;
        }
        j += n;
    }
    a0.x += a1.x + a2.x + a3.x;
    a0.y += a1.y + a2.y + a3.y;
    float inv = g_dinv[w];
    float2 yv = ((const float2*)Yb)[w * 32 + lane];
    float2 bv = ((const float2*)bias)[lane];
    float v0 = a0.x * inv + yv.x + bv.x;
    float v1 = a0.y * inv + yv.y + bv.y;
    float m = fmaxf(v0, v1);
    #pragma unroll
    for (int o = 16; o; o >>= 1) m = fmaxf(m, __shfl_xor_sync(0xffffffffu, m, o));
    float s = expf(v0 - m) + expf(v1 - m);
    #pragma unroll
    for (int o = 16; o; o >>= 1) s += __shfl_xor_sync(0xffffffffu, s, o);
    float lse = m + logf(s);
    out[w * 64 + lane * 2 + 0] = v0 - lse;
    out[w * 64 + lane * 2 + 1] = v1 - lse;
}

// ---------------- host launch ----------------
extern "C" void kernel_launch(void* const* d_in, const int* in_sizes, int n_in,
                              void* d_out, int out_size) {
    const float* x   = (const float*)d_in[0];
    const void*  ei  = d_in[1];
    const float* Wl0 = (const float*)d_in[2];
    const float* bl0 = (const float*)d_in[3];
    const float* Wr0 = (const float*)d_in[4];
    const float* Wl1 = (const float*)d_in[5];
    const float* bl1 = (const float*)d_in[6];
    const float* Wr1 = (const float*)d_in[7];
    const float* Wl2 = (const float*)d_in[8];
    const float* bl2 = (const float*)d_in[9];
    const float* Wr2 = (const float*)d_in[10];
    float* out = (float*)d_out;
    (void)in_sizes; (void)n_in; (void)out_size;

    void *p_is32, *p_deg, *p_fill, *p_zb, *p_y, *p_h;
    cudaGetSymbolAddress(&p_is32, g_is32);
    cudaGetSymbolAddress(&p_deg,  g_deg);
    cudaGetSymbolAddress(&p_fill, g_fill);
    cudaGetSymbolAddress(&p_zb,   g_zb);
    cudaGetSymbolAddress(&p_y,    g_y);
    cudaGetSymbolAddress(&p_h,    g_h);

    const int SM256 = (128 * 132 + 256 * 132) * 4;
    const int SM128 = (128 * 132 + 128 * 132) * 4;
    cudaFuncSetAttribute(k_gemm_mma<256>, cudaFuncAttributeMaxDynamicSharedMemorySize, SM256);
    cudaFuncSetAttribute(k_gemm_mma<128>, cudaFuncAttributeMaxDynamicSharedMemorySize, SM128);

    const int GT = (NNODES + 127) / 128;
    const int GW = (NNODES * 32 + 255) / 256;
    const int GE = (NEDGES + 255) / 256;
    const int GN = (NNODES + 255) / 256;

    // ---- prep ----
    cudaMemsetAsync(p_is32, 0, sizeof(int));
    cudaMemsetAsync(p_deg,  0, NNODES * sizeof(int));
    cudaMemsetAsync(p_fill, 0, NNODES * sizeof(int));
    k_detect<<<16, 256>>>((const long long*)ei);

    // layer-0 GEMM (edge-independent)
    k_gemm_mma<256><<<GT, 512, SM256>>>(x, Wl0, Wr0, (__nv_bfloat162*)p_zb, (float*)p_y);

    k_prep_edges<<<GE, 256>>>(ei);
    k_scan1<<<NBLK, SCAN_B>>>();
    k_scan3<<<GN, SCAN_B>>>();
    k_fill<<<GE, 256>>>();

    // ---- layer 0 combine ----
    k_gather_combine128<<<GW, 256>>>((const uint2*)p_zb, (const float*)p_y, bl0, (float*)p_h);

    // ---- layer 1 ----
    k_gemm_mma<256><<<GT, 512, SM256>>>((const float*)p_h, Wl1, Wr1,
                                        (__nv_bfloat162*)p_zb, (float*)p_y);
    k_gather_combine128<<<GW, 256>>>((const uint2*)p_zb, (const float*)p_y, bl1, (float*)p_h);

    // ---- layer 2 + log_softmax ----
    k_gemm_mma<128><<<GT, 512, SM128>>>((const float*)p_h, Wl2, Wr2,
                                        (__nv_bfloat162*)p_zb, (float*)p_y);
    k_gather_final64<<<GW, 256>>>((const unsigned*)p_zb, (const float*)p_y, bl2, out);
}

// round 10
// speedup vs baseline: 1.5362x; 1.5362x over previous
#include <cuda_runtime.h>
#include <cuda_bf16.h>
#include <cstdint>

// ---------------- problem constants ----------------
#define NNODES 50000
#define NEDGES 800000
#define SCAN_B 256
#define NBLK   ((NNODES + SCAN_B - 1) / SCAN_B)   // 196

// ---------------- device scratch (no allocs allowed) ----------------
__device__ int   g_src[NEDGES];
__device__ int   g_dst[NEDGES];
__device__ int   g_deg[NNODES];
__device__ int   g_rowptr[NNODES + 1];
__device__ int   g_fill[NNODES];
__device__ int   g_csrc[NEDGES];
__device__ int   g_bsum[NBLK];
__device__ float g_dinv[NNODES];
__device__ uint2 g_zb[NNODES * 32];     // z bf16: 128 cols = 32 uint2
__device__ float g_y[NNODES * 128];
__device__ float g_h[NNODES * 128];

__device__ __forceinline__ float to_tf32(float x) {
    float r;
    asm("cvt.rna.tf32.f32 %0, %1;" : "=f"(r) : "f"(x));
    return r;
}

// ---------------- edge decode + degree (dtype detected inline) ----------
__global__ void k_prep_edges(const void* __restrict__ ei_raw) {
    int i = blockIdx.x * blockDim.x + threadIdx.x;
    if (i >= NEDGES) return;
    const long long* e64 = (const long long*)ei_raw;
    bool is32 = false;
    #pragma unroll
    for (int q = 0; q < 4; ++q) {        // broadcast loads; uniform branch
        long long v = e64[q];
        if (v < 0 || v >= NNODES) is32 = true;
    }
    int d, s;
    if (is32) {
        const int* e = (const int*)ei_raw;
        d = e[i]; s = e[NEDGES + i];
    } else {
        d = (int)e64[i]; s = (int)e64[NEDGES + i];
    }
    g_dst[i] = d;
    g_src[i] = s;
    atomicAdd(&g_deg[d], 1);
}

// ---------------- CSR build ----------------
__global__ void k_scan1() {
    __shared__ int s[SCAN_B];
    int tid = threadIdx.x;
    int i = blockIdx.x * SCAN_B + tid;
    int v = (i < NNODES) ? g_deg[i] : 0;
    s[tid] = v;
    __syncthreads();
    #pragma unroll
    for (int off = 1; off < SCAN_B; off <<= 1) {
        int t = (tid >= off) ? s[tid - off] : 0;
        __syncthreads();
        s[tid] += t;
        __syncthreads();
    }
    if (i < NNODES) g_rowptr[i + 1] = s[tid];
    if (tid == SCAN_B - 1) g_bsum[blockIdx.x] = s[tid];
}

__global__ void k_scan3() {
    __shared__ int red[SCAN_B];
    int tid = threadIdx.x;
    int part = (tid < (int)blockIdx.x && tid < NBLK) ? g_bsum[tid] : 0;
    red[tid] = part;
    __syncthreads();
    #pragma unroll
    for (int off = SCAN_B / 2; off > 0; off >>= 1) {
        if (tid < off) red[tid] += red[tid + off];
        __syncthreads();
    }
    int offset = red[0];
    int i = blockIdx.x * SCAN_B + tid;
    if (i == 0) g_rowptr[0] = 0;
    if (i < NNODES) {
        g_rowptr[i + 1] += offset;
        g_dinv[i] = 1.0f / fmaxf((float)g_deg[i], 1.0f);
    }
}
__global__ void k_fill() {
    int i = blockIdx.x * blockDim.x + threadIdx.x;
    if (i >= NEDGES) return;
    int d = g_dst[i];
    int pos = g_rowptr[d] + atomicAdd(&g_fill[d], 1);
    g_csrc[pos] = g_src[i];
}

// ---------------- mma.sync tf32 dual GEMM ----------------
template <int NC>
__global__ __launch_bounds__(512, 1)
void k_gemm_mma(const float* __restrict__ H,
                const float* __restrict__ Wl, const float* __restrict__ Wr,
                __nv_bfloat162* __restrict__ Zb, float* __restrict__ Y) {
    constexpr int D   = NC / 2;
    constexpr int NT  = NC / 32;
    constexpr int ST  = 132;

    extern __shared__ float smem[];
    float* sA = smem;
    float* sB = smem + 128 * ST;

    const int tid  = threadIdx.x;
    const int wid  = tid >> 5;
    const int lane = tid & 31;
    const int row0 = blockIdx.x * 128;

    {
        const float4* h4 = (const float4*)H;
        #pragma unroll
        for (int i = tid; i < 128 * 32; i += 512) {
            int r = i >> 5, c = i & 31;
            int gr = row0 + r;
            float4 v = make_float4(0.f, 0.f, 0.f, 0.f);
            if (gr < NNODES) v = h4[gr * 32 + c];
            float* p = &sA[r * ST + c * 4];
            p[0] = to_tf32(v.x); p[1] = to_tf32(v.y);
            p[2] = to_tf32(v.z); p[3] = to_tf32(v.w);
        }
    }
    {
        #pragma unroll
        for (int i = tid; i < NC * 32; i += 512) {
            int n = i >> 5, c = i & 31;
            const float4* wsrc = (const float4*)((n < D) ? (Wl + n * 128)
                                                         : (Wr + (n - D) * 128));
            float4 v = wsrc[c];
            float* p = &sB[n * ST + c * 4];
            p[0] = to_tf32(v.x); p[1] = to_tf32(v.y);
            p[2] = to_tf32(v.z); p[3] = to_tf32(v.w);
        }
    }
    __syncthreads();

    const int warp_m = wid & 3;
    const int warp_n = wid >> 2;
    const int lm = lane >> 2;
    const int lk = lane & 3;

    float acc[2][NT][4];
    #pragma unroll
    for (int mi = 0; mi < 2; ++mi)
        #pragma unroll
        for (int ni = 0; ni < NT; ++ni)
            #pragma unroll
            for (int q = 0; q < 4; ++q) acc[mi][ni][q] = 0.f;

    #pragma unroll
    for (int kk = 0; kk < 16; ++kk) {
        const int k0 = kk * 8;
        uint32_t a[2][4];
        #pragma unroll
        for (int mi = 0; mi < 2; ++mi) {
            const int rb = warp_m * 32 + mi * 16;
            a[mi][0] = *(const uint32_t*)&sA[(rb + lm)     * ST + k0 + lk];
            a[mi][1] = *(const uint32_t*)&sA[(rb + 8 + lm) * ST + k0 + lk];
            a[mi][2] = *(const uint32_t*)&sA[(rb + lm)     * ST + k0 + 4 + lk];
            a[mi][3] = *(const uint32_t*)&sA[(rb + 8 + lm) * ST + k0 + 4 + lk];
        }
        uint32_t b[NT][2];
        #pragma unroll
        for (int ni = 0; ni < NT; ++ni) {
            const int nb = warp_n * (NT * 8) + ni * 8;
            b[ni][0] = *(const uint32_t*)&sB[(nb + lm) * ST + k0 + lk];
            b[ni][1] = *(const uint32_t*)&sB[(nb + lm) * ST + k0 + 4 + lk];
        }
        #pragma unroll
        for (int mi = 0; mi < 2; ++mi)
            #pragma unroll
            for (int ni = 0; ni < NT; ++ni) {
                asm volatile(
                    "mma.sync.aligned.m16n8k8.row.col.f32.tf32.tf32.f32 "
                    "{%0,%1,%2,%3}, {%4,%5,%6,%7}, {%8,%9}, {%0,%1,%2,%3};"
                    : "+f"(acc[mi][ni][0]), "+f"(acc[mi][ni][1]),
                      "+f"(acc[mi][ni][2]), "+f"(acc[mi][ni][3])
                    : "r"(a[mi][0]), "r"(a[mi][1]), "r"(a[mi][2]), "r"(a[mi][3]),
                      "r"(b[ni][0]), "r"(b[ni][1]));
            }
    }

    {
        const bool yhalf = (warp_n >= 2);
        const int cbase = warp_n * (NT * 8) - (yhalf ? D : 0);
        #pragma unroll
        for (int mi = 0; mi < 2; ++mi) {
            const int rl = row0 + warp_m * 32 + mi * 16 + lm;
            const int rh = rl + 8;
            #pragma unroll
            for (int ni = 0; ni < NT; ++ni) {
                const int oc = cbase + ni * 8 + lk * 2;
                if (yhalf) {
                    if (rl < NNODES)
                        *(float2*)&Y[rl * D + oc] = make_float2(acc[mi][ni][0], acc[mi][ni][1]);
                    if (rh < NNODES)
                        *(float2*)&Y[rh * D + oc] = make_float2(acc[mi][ni][2], acc[mi][ni][3]);
                } else {
                    if (rl < NNODES)
                        Zb[rl * (D / 2) + oc / 2] =
                            __float22bfloat162_rn(make_float2(acc[mi][ni][0], acc[mi][ni][1]));
                    if (rh < NNODES)
                        Zb[rh * (D / 2) + oc / 2] =
                            __float22bfloat162_rn(make_float2(acc[mi][ni][2], acc[mi][ni][3]));
                }
            }
        }
    }
}

// -------- gather + combine + relu (D=128): warp/node, 4-wide MLP ----------
__global__ __launch_bounds__(256)
void k_gather_combine128(const uint2* __restrict__ Zb, const float* __restrict__ Yb,
                         const float* __restrict__ bias, float* __restrict__ Hout) {
    const int w    = (blockIdx.x * blockDim.x + threadIdx.x) >> 5;
    const int lane = threadIdx.x & 31;
    if (w >= NNODES) return;
    int j = g_rowptr[w];
    const int e = g_rowptr[w + 1];
    float4 a0 = make_float4(0.f, 0.f, 0.f, 0.f);
    float4 a1 = make_float4(0.f, 0.f, 0.f, 0.f);
    float4 a2 = make_float4(0.f, 0.f, 0.f, 0.f);
    float4 a3 = make_float4(0.f, 0.f, 0.f, 0.f);
    for (; j + 3 < e; j += 4) {
        // uniform-address index loads: HW broadcasts, 1 wavefront each
        int s0 = g_csrc[j];
        int s1 = g_csrc[j + 1];
        int s2 = g_csrc[j + 2];
        int s3 = g_csrc[j + 3];
        uint2 u0 = Zb[s0 * 32 + lane];
        uint2 u1 = Zb[s1 * 32 + lane];
        uint2 u2 = Zb[s2 * 32 + lane];
        uint2 u3 = Zb[s3 * 32 + lane];
        float2 f;
        f = __bfloat1622float2(*(const __nv_bfloat162*)&u0.x); a0.x += f.x; a0.y += f.y;
        f = __bfloat1622float2(*(const __nv_bfloat162*)&u0.y); a0.z += f.x; a0.w += f.y;
        f = __bfloat1622float2(*(const __nv_bfloat162*)&u1.x); a1.x += f.x; a1.y += f.y;
        f = __bfloat1622float2(*(const __nv_bfloat162*)&u1.y); a1.z += f.x; a1.w += f.y;
        f = __bfloat1622float2(*(const __nv_bfloat162*)&u2.x); a2.x += f.x; a2.y += f.y;
        f = __bfloat1622float2(*(const __nv_bfloat162*)&u2.y); a2.z += f.x; a2.w += f.y;
        f = __bfloat1622float2(*(const __nv_bfloat162*)&u3.x); a3.x += f.x; a3.y += f.y;
        f = __bfloat1622float2(*(const __nv_bfloat162*)&u3.y); a3.z += f.x; a3.w += f.y;
    }
    for (; j < e; ++j) {
        int s0 = g_csrc[j];
        uint2 u0 = Zb[s0 * 32 + lane];
        float2 f;
        f = __bfloat1622float2(*(const __nv_bfloat162*)&u0.x); a0.x += f.x; a0.y += f.y;
        f = __bfloat1622float2(*(const __nv_bfloat162*)&u0.y); a0.z += f.x; a0.w += f.y;
    }
    a0.x += a1.x + a2.x + a3.x;
    a0.y += a1.y + a2.y + a3.y;
    a0.z += a1.z + a2.z + a3.z;
    a0.w += a1.w + a2.w + a3.w;
    float inv = g_dinv[w];
    float4 yv = ((const float4*)Yb)[w * 32 + lane];
    float4 bv = ((const float4*)bias)[lane];
    float4 o;
    o.x = fmaxf(a0.x * inv + yv.x + bv.x, 0.f);
    o.y = fmaxf(a0.y * inv + yv.y + bv.y, 0.f);
    o.z = fmaxf(a0.z * inv + yv.z + bv.z, 0.f);
    o.w = fmaxf(a0.w * inv + yv.w + bv.w, 0.f);
    ((float4*)Hout)[w * 32 + lane] = o;
}

// -------- gather + combine + log_softmax (D=64): 4-wide MLP --------
__global__ __launch_bounds__(256)
void k_gather_final64(const unsigned* __restrict__ Zb, const float* __restrict__ Yb,
                      const float* __restrict__ bias, float* __restrict__ out) {
    const int w    = (blockIdx.x * blockDim.x + threadIdx.x) >> 5;
    const int lane = threadIdx.x & 31;
    if (w >= NNODES) return;
    int j = g_rowptr[w];
    const int e = g_rowptr[w + 1];
    float2 a0 = make_float2(0.f, 0.f);
    float2 a1 = make_float2(0.f, 0.f);
    float2 a2 = make_float2(0.f, 0.f);
    float2 a3 = make_float2(0.f, 0.f);
    for (; j + 3 < e; j += 4) {
        int s0 = g_csrc[j];
        int s1 = g_csrc[j + 1];
        int s2 = g_csrc[j + 2];
        int s3 = g_csrc[j + 3];
        unsigned u0 = Zb[s0 * 32 + lane];
        unsigned u1 = Zb[s1 * 32 + lane];
        unsigned u2 = Zb[s2 * 32 + lane];
        unsigned u3 = Zb[s3 * 32 + lane];
        float2 f;
        f = __bfloat1622float2(*(const __nv_bfloat162*)&u0); a0.x += f.x; a0.y += f.y;
        f = __bfloat1622float2(*(const __nv_bfloat162*)&u1); a1.x += f.x; a1.y += f.y;
        f = __bfloat1622float2(*(const __nv_bfloat162*)&u2); a2.x += f.x; a2.y += f.y;
        f = __bfloat1622float2(*(const __nv_bfloat162*)&u3); a3.x += f.x; a3.y += f.y;
    }
    for (; j < e; ++j) {
        int s0 = g_csrc[j];
        unsigned u0 = Zb[s0 * 32 + lane];
        float2 f = __bfloat1622float2(*(const __nv_bfloat162*)&u0);
        a0.x += f.x; a0.y += f.y;
    }
    a0.x += a1.x + a2.x + a3.x;
    a0.y += a1.y + a2.y + a3.y;
    float inv = g_dinv[w];
    float2 yv = ((const float2*)Yb)[w * 32 + lane];
    float2 bv = ((const float2*)bias)[lane];
    float v0 = a0.x * inv + yv.x + bv.x;
    float v1 = a0.y * inv + yv.y + bv.y;
    float m = fmaxf(v0, v1);
    #pragma unroll
    for (int o = 16; o; o >>= 1) m = fmaxf(m, __shfl_xor_sync(0xffffffffu, m, o));
    float s = expf(v0 - m) + expf(v1 - m);
    #pragma unroll
    for (int o = 16; o; o >>= 1) s += __shfl_xor_sync(0xffffffffu, s, o);
    float lse = m + logf(s);
    out[w * 64 + lane * 2 + 0] = v0 - lse;
    out[w * 64 + lane * 2 + 1] = v1 - lse;
}

// ---------------- host launch ----------------
extern "C" void kernel_launch(void* const* d_in, const int* in_sizes, int n_in,
                              void* d_out, int out_size) {
    const float* x   = (const float*)d_in[0];
    const void*  ei  = d_in[1];
    const float* Wl0 = (const float*)d_in[2];
    const float* bl0 = (const float*)d_in[3];
    const float* Wr0 = (const float*)d_in[4];
    const float* Wl1 = (const float*)d_in[5];
    const float* bl1 = (const float*)d_in[6];
    const float* Wr1 = (const float*)d_in[7];
    const float* Wl2 = (const float*)d_in[8];
    const float* bl2 = (const float*)d_in[9];
    const float* Wr2 = (const float*)d_in[10];
    float* out = (float*)d_out;
    (void)in_sizes; (void)n_in; (void)out_size;

    void *p_deg, *p_fill, *p_zb, *p_y, *p_h;
    cudaGetSymbolAddress(&p_deg,  g_deg);
    cudaGetSymbolAddress(&p_fill, g_fill);
    cudaGetSymbolAddress(&p_zb,   g_zb);
    cudaGetSymbolAddress(&p_y,    g_y);
    cudaGetSymbolAddress(&p_h,    g_h);

    const int SM256 = (128 * 132 + 256 * 132) * 4;
    const int SM128 = (128 * 132 + 128 * 132) * 4;
    cudaFuncSetAttribute(k_gemm_mma<256>, cudaFuncAttributeMaxDynamicSharedMemorySize, SM256);
    cudaFuncSetAttribute(k_gemm_mma<128>, cudaFuncAttributeMaxDynamicSharedMemorySize, SM128);

    const int GT = (NNODES + 127) / 128;
    const int GW = (NNODES * 32 + 255) / 256;
    const int GE = (NEDGES + 255) / 256;

    // ---- prep ----
    cudaMemsetAsync(p_deg,  0, NNODES * sizeof(int));
    cudaMemsetAsync(p_fill, 0, NNODES * sizeof(int));

    // layer-0 GEMM (edge-independent)
    k_gemm_mma<256><<<GT, 512, SM256>>>(x, Wl0, Wr0, (__nv_bfloat162*)p_zb, (float*)p_y);

    k_prep_edges<<<GE, 256>>>(ei);
    k_scan1<<<NBLK, SCAN_B>>>();
    k_scan3<<<(NNODES + SCAN_B - 1) / SCAN_B, SCAN_B>>>();
    k_fill<<<GE, 256>>>();

    // ---- layer 0 combine ----
    k_gather_combine128<<<GW, 256>>>((const uint2*)p_zb, (const float*)p_y, bl0, (float*)p_h);

    // ---- layer 1 ----
    k_gemm_mma<256><<<GT, 512, SM256>>>((const float*)p_h, Wl1, Wr1,
                                        (__nv_bfloat162*)p_zb, (float*)p_y);
    k_gather_combine128<<<GW, 256>>>((const uint2*)p_zb, (const float*)p_y, bl1, (float*)p_h);

    // ---- layer 2 + log_softmax ----
    k_gemm_mma<128><<<GT, 512, SM128>>>((const float*)p_h, Wl2, Wr2,
                                        (__nv_bfloat162*)p_zb, (float*)p_y);
    k_gather_final64<<<GW, 256>>>((const unsigned*)p_zb, (const float*)p_y, bl2, out);
}